// round 1
// baseline (speedup 1.0000x reference)
#include <cuda_runtime.h>

#define N_AST   200000
#define N_TEST  10000
#define HD      128
#define NLAYERS 5

// ---------------- scratch (device globals; no allocation allowed) ----------
// float buffer layout (in floats)
#define F_HA   0u
#define F_HB   25600000u
#define F_RA   51200000u
#define F_X    76800000u
#define F_HTA  102400000u
#define F_HTB  103680000u
#define F_RT   104960000u
#define F_XT   106240000u
#define F_TOT  107520000u
__device__ float g_f[F_TOT];

// int buffer layout (in ints)
#define I_OFF_AA 0
#define I_OFF_TA 200001
#define I_OFF_AT 400002
#define I_CUR_AA 410003
#define I_CUR_TA 610003
#define I_CUR_AT 810003
#define I_CSR_AA 820013
#define I_CSR_TA 2820013
#define I_CSR_AT 3320013
#define I_TOT    3820013
__device__ int g_i[I_TOT];

static inline int div_up(int a, int b) { return (a + b - 1) / b; }

// ---------------- small utility kernels ------------------------------------
__global__ void k_zero_int(int* __restrict__ p, int n) {
    int i = blockIdx.x * blockDim.x + threadIdx.x;
    if (i < n) p[i] = 0;
}

__global__ void k_copy_int(const int* __restrict__ a, int* __restrict__ b, int n) {
    int i = blockIdx.x * blockDim.x + threadIdx.x;
    if (i < n) b[i] = a[i];
}

__global__ void k_hist(const int* __restrict__ dst, int* __restrict__ deg, int E) {
    int e = blockIdx.x * blockDim.x + threadIdx.x;
    if (e < E) atomicAdd(&deg[dst[e]], 1);
}

// single-block exclusive scan over n elements (n up to ~200k, 1024 threads)
__global__ void k_exscan(const int* __restrict__ v, int* __restrict__ offs, int n) {
    __shared__ int wsum[32];
    __shared__ int carry;
    int t = threadIdx.x;
    if (t == 0) carry = 0;
    __syncthreads();
    for (int base = 0; base < n; base += 1024) {
        int i = base + t;
        int orig = (i < n) ? v[i] : 0;
        int x = orig;
        #pragma unroll
        for (int o = 1; o < 32; o <<= 1) {
            int y = __shfl_up_sync(0xffffffffu, x, o);
            if ((t & 31) >= o) x += y;
        }
        if ((t & 31) == 31) wsum[t >> 5] = x;
        __syncthreads();
        if (t < 32) {
            int w = wsum[t];
            #pragma unroll
            for (int o = 1; o < 32; o <<= 1) {
                int y = __shfl_up_sync(0xffffffffu, w, o);
                if (t >= o) w += y;
            }
            wsum[t] = w;
        }
        __syncthreads();
        int woff = (t >= 32) ? wsum[(t >> 5) - 1] : 0;
        int incl = x + woff + carry;
        if (i < n) offs[i] = incl - orig;
        __syncthreads();
        if (t == 1023) carry = incl;
        __syncthreads();
    }
    if (t == 0) offs[n] = carry;
}

// counting-sort scatter: csr[pos] = src[e] grouped by dst
__global__ void k_build(const int* __restrict__ dst, const int* __restrict__ src,
                        int* __restrict__ cursor, int* __restrict__ csr, int E) {
    int e = blockIdx.x * blockDim.x + threadIdx.x;
    if (e < E) {
        int p = atomicAdd(&cursor[dst[e]], 1);
        csr[p] = src[e];
    }
}

__global__ void k_init_test(const float* __restrict__ temb, float* __restrict__ h) {
    int i = blockIdx.x * blockDim.x + threadIdx.x;
    if (i < N_TEST * HD) h[i] = temb[i & 127];
}

// ---------------- encoder: h_ast = [emb[label] || content @ Wc + bc] -------
// 16 nodes per block, 256 threads. Wc (256x64) fully in smem.
__global__ void __launch_bounds__(256) k_encode(
    const int* __restrict__ label, const float* __restrict__ content,
    const float* __restrict__ emb, const float* __restrict__ Wc,
    const float* __restrict__ bc, float* __restrict__ h)
{
    extern __shared__ float sm[];
    float* Ws = sm;            // 256*64
    float* Cs = sm + 16384;    // 16*256
    int t = threadIdx.x;
    const float4* Wc4 = (const float4*)Wc;
    float4* Ws4 = (float4*)Ws;
    #pragma unroll
    for (int i = 0; i < 16; i++) Ws4[t + 256 * i] = Wc4[t + 256 * i];
    int n0 = blockIdx.x * 16;
    const float4* C4 = (const float4*)content + (size_t)n0 * 64;
    float4* Cs4 = (float4*)Cs;
    #pragma unroll
    for (int i = 0; i < 4; i++) Cs4[t + 256 * i] = C4[t + 256 * i];
    __syncthreads();
    int node = t >> 4, c = t & 15;
    const float* crow = &Cs[node * 256];
    float a0 = bc[c], a1 = bc[c + 16], a2 = bc[c + 32], a3 = bc[c + 48];
    #pragma unroll 4
    for (int k = 0; k < 256; k++) {
        float cv = crow[k];
        const float* wr = &Ws[k * 64];
        a0 += cv * wr[c];
        a1 += cv * wr[c + 16];
        a2 += cv * wr[c + 32];
        a3 += cv * wr[c + 48];
    }
    int gn = n0 + node;
    int lab = label[gn];
    float* hr = &h[(size_t)gn * HD];
    const float* er = &emb[(size_t)lab * 64];
    hr[c]      = er[c];
    hr[c + 16] = er[c + 16];
    hr[c + 32] = er[c + 32];
    hr[c + 48] = er[c + 48];
    hr[64 + c]      = a0;
    hr[64 + c + 16] = a1;
    hr[64 + c + 32] = a2;
    hr[64 + c + 48] = a3;
}

// ---------------- GEMM: C[Mx128] = A[Mx128] @ W[128x128] -------------------
// 64 rows/block, 256 threads, 8x4 register tile per thread, W in smem.
__global__ void __launch_bounds__(256) k_gemm128(
    const float* __restrict__ A, const float* __restrict__ W,
    float* __restrict__ C, int M)
{
    extern __shared__ float sm[];
    float* Ws = sm;            // 128*128
    float* As = sm + 16384;    // 64*132 (pad 4)
    int t = threadIdx.x;
    const float4* W4 = (const float4*)W;
    float4* Ws4 = (float4*)Ws;
    #pragma unroll
    for (int i = 0; i < 16; i++) Ws4[t + 256 * i] = W4[t + 256 * i];
    int m0 = blockIdx.x * 64;
    #pragma unroll
    for (int i = 0; i < 8; i++) {
        int idx = t + 256 * i;
        int r = idx >> 5, cc = idx & 31;
        int gr = m0 + r;
        float4 v = (gr < M) ? ((const float4*)A)[(size_t)gr * 32 + cc]
                            : make_float4(0.f, 0.f, 0.f, 0.f);
        *(float4*)&As[r * 132 + cc * 4] = v;
    }
    __syncthreads();
    int c0 = (t & 31) * 4;
    int r0 = (t >> 5) * 8;
    float acc[8][4];
    #pragma unroll
    for (int i = 0; i < 8; i++) { acc[i][0] = acc[i][1] = acc[i][2] = acc[i][3] = 0.f; }
    #pragma unroll 2
    for (int k = 0; k < 128; k++) {
        float4 w = *(const float4*)&Ws[k * 128 + c0];
        #pragma unroll
        for (int i = 0; i < 8; i++) {
            float a = As[(r0 + i) * 132 + k];
            acc[i][0] += a * w.x;
            acc[i][1] += a * w.y;
            acc[i][2] += a * w.z;
            acc[i][3] += a * w.w;
        }
    }
    #pragma unroll
    for (int i = 0; i < 8; i++) {
        int gr = m0 + r0 + i;
        if (gr < M)
            *(float4*)&C[(size_t)gr * HD + c0] =
                make_float4(acc[i][0], acc[i][1], acc[i][2], acc[i][3]);
    }
}

// ---------------- fused aggregate for ast nodes ------------------------------
// warp per node: mean over aa-CSR of Xaa rows + mean over ta-CSR of Xta rows
// + bias, relu, optional residual add/save.
__global__ void k_agg_ast(const float* __restrict__ Xaa, const float* __restrict__ Xta,
    const int* __restrict__ offs_aa, const int* __restrict__ csr_aa,
    const int* __restrict__ offs_ta, const int* __restrict__ csr_ta,
    const float* __restrict__ b, const float* __restrict__ res,
    float* __restrict__ out, float* __restrict__ res_out,
    int add_res, int save_res)
{
    int node = (blockIdx.x * blockDim.x + threadIdx.x) >> 5;
    if (node >= N_AST) return;
    int lane = threadIdx.x & 31;
    float4 r;
    {
        int s0 = offs_aa[node], s1 = offs_aa[node + 1];
        float4 a = make_float4(0.f, 0.f, 0.f, 0.f);
        for (int e0 = s0; e0 < s1; e0 += 32) {
            int idx = (e0 + lane < s1) ? csr_aa[e0 + lane] : 0;
            int m = min(32, s1 - e0);
            for (int j = 0; j < m; j++) {
                int s = __shfl_sync(0xffffffffu, idx, j);
                float4 v = *(const float4*)&Xaa[(size_t)s * HD + lane * 4];
                a.x += v.x; a.y += v.y; a.z += v.z; a.w += v.w;
            }
        }
        float inv = 1.f / (float)((s1 - s0) > 0 ? (s1 - s0) : 1);
        r = make_float4(a.x * inv, a.y * inv, a.z * inv, a.w * inv);
    }
    {
        int s0 = offs_ta[node], s1 = offs_ta[node + 1];
        float4 a = make_float4(0.f, 0.f, 0.f, 0.f);
        for (int e0 = s0; e0 < s1; e0 += 32) {
            int idx = (e0 + lane < s1) ? csr_ta[e0 + lane] : 0;
            int m = min(32, s1 - e0);
            for (int j = 0; j < m; j++) {
                int s = __shfl_sync(0xffffffffu, idx, j);
                float4 v = *(const float4*)&Xta[(size_t)s * HD + lane * 4];
                a.x += v.x; a.y += v.y; a.z += v.z; a.w += v.w;
            }
        }
        float inv = 1.f / (float)((s1 - s0) > 0 ? (s1 - s0) : 1);
        r.x += a.x * inv; r.y += a.y * inv; r.z += a.z * inv; r.w += a.w * inv;
    }
    float4 bb = *(const float4*)&b[lane * 4];
    r.x = fmaxf(r.x + bb.x, 0.f);
    r.y = fmaxf(r.y + bb.y, 0.f);
    r.z = fmaxf(r.z + bb.z, 0.f);
    r.w = fmaxf(r.w + bb.w, 0.f);
    size_t o = (size_t)node * HD + lane * 4;
    if (add_res) {
        float4 rv = *(const float4*)&res[o];
        r.x += rv.x; r.y += rv.y; r.z += rv.z; r.w += rv.w;
    }
    *(float4*)&out[o] = r;
    if (save_res) *(float4*)&res_out[o] = r;
}

// ---------------- fused aggregate for test nodes ---------------------------
__global__ void k_agg_test(const float* __restrict__ Xat,
    const int* __restrict__ offs_at, const int* __restrict__ csr_at,
    const float* __restrict__ b, const float* __restrict__ res,
    float* __restrict__ out, float* __restrict__ res_out,
    int add_res, int save_res)
{
    int node = (blockIdx.x * blockDim.x + threadIdx.x) >> 5;
    if (node >= N_TEST) return;
    int lane = threadIdx.x & 31;
    int s0 = offs_at[node], s1 = offs_at[node + 1];
    float4 a = make_float4(0.f, 0.f, 0.f, 0.f);
    for (int e0 = s0; e0 < s1; e0 += 32) {
        int idx = (e0 + lane < s1) ? csr_at[e0 + lane] : 0;
        int m = min(32, s1 - e0);
        for (int j = 0; j < m; j++) {
            int s = __shfl_sync(0xffffffffu, idx, j);
            float4 v = *(const float4*)&Xat[(size_t)s * HD + lane * 4];
            a.x += v.x; a.y += v.y; a.z += v.z; a.w += v.w;
        }
    }
    float inv = 1.f / (float)((s1 - s0) > 0 ? (s1 - s0) : 1);
    float4 bb = *(const float4*)&b[lane * 4];
    float4 r;
    r.x = fmaxf(a.x * inv + bb.x, 0.f);
    r.y = fmaxf(a.y * inv + bb.y, 0.f);
    r.z = fmaxf(a.z * inv + bb.z, 0.f);
    r.w = fmaxf(a.w * inv + bb.w, 0.f);
    size_t o = (size_t)node * HD + lane * 4;
    if (add_res) {
        float4 rv = *(const float4*)&res[o];
        r.x += rv.x; r.y += rv.y; r.z += rv.z; r.w += rv.w;
    }
    *(float4*)&out[o] = r;
    if (save_res) *(float4*)&res_out[o] = r;
}

// ---------------- decoder: logits + softmax ---------------------------------
__global__ void k_decode(const float* __restrict__ h, const float* __restrict__ dW,
                         const float* __restrict__ db, float* __restrict__ logits,
                         float* __restrict__ pred, int write_pred)
{
    int node = (blockIdx.x * blockDim.x + threadIdx.x) >> 5;
    if (node >= N_AST) return;
    int lane = threadIdx.x & 31;
    float4 v = *(const float4*)&h[(size_t)node * HD + lane * 4];
    float l0 = 0.f, l1 = 0.f;
    const float* hv = &v.x;
    #pragma unroll
    for (int j = 0; j < 4; j++) {
        int k = lane * 4 + j;
        float2 w = *(const float2*)&dW[k * 2];
        l0 += hv[j] * w.x;
        l1 += hv[j] * w.y;
    }
    #pragma unroll
    for (int o = 16; o; o >>= 1) {
        l0 += __shfl_xor_sync(0xffffffffu, l0, o);
        l1 += __shfl_xor_sync(0xffffffffu, l1, o);
    }
    if (lane == 0) {
        l0 += db[0];
        l1 += db[1];
        logits[node * 2]     = l0;
        logits[node * 2 + 1] = l1;
        if (write_pred) {
            float m = fmaxf(l0, l1);
            float e0 = expf(l0 - m), e1 = expf(l1 - m);
            float s = e0 + e1;
            pred[node * 2]     = e0 / s;
            pred[node * 2 + 1] = e1 / s;
        }
    }
}

// ---------------- launch ----------------------------------------------------
extern "C" void kernel_launch(void* const* d_in, const int* in_sizes, int n_in,
                              void* d_out, int out_size)
{
    const int*   ast_label   = (const int*)d_in[0];
    const float* ast_content = (const float*)d_in[1];
    const int* src_aa = (const int*)d_in[2];
    const int* dst_aa = (const int*)d_in[3];
    const int* src_at = (const int*)d_in[4];
    const int* dst_at = (const int*)d_in[5];
    const int* src_ta = (const int*)d_in[6];
    const int* dst_ta = (const int*)d_in[7];
    int E_aa = in_sizes[2], E_at = in_sizes[4], E_ta = in_sizes[6];

    int p = 8;
    if (n_in > 8 && in_sizes[8] == 1) p = 9;  // skip n_test scalar if present
    const float* emb    = (const float*)d_in[p + 0];
    const float* Wc     = (const float*)d_in[p + 1];
    const float* bc     = (const float*)d_in[p + 2];
    const float* temb   = (const float*)d_in[p + 3];
    const float* W_aa   = (const float*)d_in[p + 4];
    const float* W_at   = (const float*)d_in[p + 5];
    const float* W_ta   = (const float*)d_in[p + 6];
    const float* b_ast  = (const float*)d_in[p + 7];
    const float* b_test = (const float*)d_in[p + 8];
    const float* dW     = (const float*)d_in[p + 9];
    const float* db     = (const float*)d_in[p + 10];

    float* F = nullptr;
    int*   I = nullptr;
    cudaGetSymbolAddress((void**)&F, g_f);
    cudaGetSymbolAddress((void**)&I, g_i);

    cudaFuncSetAttribute(k_gemm128, cudaFuncAttributeMaxDynamicSharedMemorySize, 99328);
    cudaFuncSetAttribute(k_encode,  cudaFuncAttributeMaxDynamicSharedMemorySize, 81920);

    float* hA  = F + F_HA;  float* hB  = F + F_HB;
    float* rA  = F + F_RA;  float* X   = F + F_X;
    float* hTA = F + F_HTA; float* hTB = F + F_HTB;
    float* rT  = F + F_RT;  float* XT  = F + F_XT;

    int* off_aa = I + I_OFF_AA; int* off_ta = I + I_OFF_TA; int* off_at = I + I_OFF_AT;
    int* cur_aa = I + I_CUR_AA; int* cur_ta = I + I_CUR_TA; int* cur_at = I + I_CUR_AT;
    int* csr_aa = I + I_CSR_AA; int* csr_ta = I + I_CSR_TA; int* csr_at = I + I_CSR_AT;

    // --- CSR build (per call; edge lists constant within call) ---
    k_zero_int<<<div_up(N_AST, 256), 256>>>(cur_aa, N_AST);
    k_zero_int<<<div_up(N_AST, 256), 256>>>(cur_ta, N_AST);
    k_zero_int<<<div_up(N_TEST, 256), 256>>>(cur_at, N_TEST);
    k_hist<<<div_up(E_aa, 256), 256>>>(dst_aa, cur_aa, E_aa);
    k_hist<<<div_up(E_ta, 256), 256>>>(dst_ta, cur_ta, E_ta);
    k_hist<<<div_up(E_at, 256), 256>>>(dst_at, cur_at, E_at);
    k_exscan<<<1, 1024>>>(cur_aa, off_aa, N_AST);
    k_exscan<<<1, 1024>>>(cur_ta, off_ta, N_AST);
    k_exscan<<<1, 1024>>>(cur_at, off_at, N_TEST);
    k_copy_int<<<div_up(N_AST, 256), 256>>>(off_aa, cur_aa, N_AST);
    k_copy_int<<<div_up(N_AST, 256), 256>>>(off_ta, cur_ta, N_AST);
    k_copy_int<<<div_up(N_TEST, 256), 256>>>(off_at, cur_at, N_TEST);
    k_build<<<div_up(E_aa, 256), 256>>>(dst_aa, src_aa, cur_aa, csr_aa, E_aa);
    k_build<<<div_up(E_ta, 256), 256>>>(dst_ta, src_ta, cur_ta, csr_ta, E_ta);
    k_build<<<div_up(E_at, 256), 256>>>(dst_at, src_at, cur_at, csr_at, E_at);

    // --- encode node features ---
    k_encode<<<N_AST / 16, 256, 81920>>>(ast_label, ast_content, emb, Wc, bc, hA);
    k_init_test<<<div_up(N_TEST * HD, 256), 256>>>(temb, hTA);

    // --- 5 GCN layers with residuals at 1,3 ---
    const float* ia = hA; const float* it = hTA;
    float* oa = hB; float* ot = hTB;
    for (int l = 0; l < NLAYERS; l++) {
        int add  = (l == 1 || l == 3);
        int save = (l == 0 || l == 2);
        k_gemm128<<<div_up(N_AST, 64), 256, 99328>>>(ia, W_aa + (size_t)l * HD * HD, X, N_AST);
        k_gemm128<<<div_up(N_TEST, 64), 256, 99328>>>(it, W_ta + (size_t)l * HD * HD, XT, N_TEST);
        k_agg_ast<<<div_up(N_AST * 32, 256), 256>>>(X, XT, off_aa, csr_aa, off_ta, csr_ta,
                                                    b_ast + l * HD, rA, oa, rA, add, save);
        k_gemm128<<<div_up(N_AST, 64), 256, 99328>>>(ia, W_at + (size_t)l * HD * HD, X, N_AST);
        k_agg_test<<<div_up(N_TEST * 32, 256), 256>>>(X, off_at, csr_at,
                                                      b_test + l * HD, rT, ot, rT, add, save);
        const float* ta = ia; ia = oa; oa = (float*)ta;
        const float* tt = it; it = ot; ot = (float*)tt;
    }

    // --- decode: logits then softmax probs ---
    float* logits = (float*)d_out;
    int write_pred = (out_size >= 4 * N_AST);
    float* pred = logits + 2 * N_AST;
    k_decode<<<div_up(N_AST * 32, 256), 256>>>(ia, dW, db, logits, pred, write_pred);
}

// round 3
// speedup vs baseline: 1.1904x; 1.1904x over previous
#include <cuda_runtime.h>

#define N_AST   200000
#define N_TEST  10000
#define HD      128
#define NLAYERS 5

// ---------------- scratch (device globals; no allocation allowed) ----------
#define F_HA   0u
#define F_HB   25600000u
#define F_RA   51200000u
#define F_S    76800000u
#define F_MTA  102400000u
#define F_HTA  128000000u
#define F_HTB  129280000u
#define F_RT   130560000u
#define F_XTA  131840000u
#define F_ST   133120000u
#define F_TOT  134400000u
__device__ float g_f[F_TOT];

#define I_OFF_AA 0
#define I_OFF_TA 200001
#define I_OFF_AT 400002
#define I_CUR_AA 410003
#define I_CUR_TA 610003
#define I_CUR_AT 810003
#define I_CSR_AA 820013
#define I_CSR_TA 2820013
#define I_CSR_AT 3320013
#define I_TOT    3820013
__device__ int g_i[I_TOT];

static inline int div_up(int a, int b) { return (a + b - 1) / b; }

// epilogue flags
#define F_ADDIN  1
#define F_BIAS   2
#define F_RELU   4
#define F_ADDRES 8
#define F_SAVE   16

// ---------------- small utility kernels ------------------------------------
__global__ void k_zero_int(int* __restrict__ p, int n) {
    int i = blockIdx.x * blockDim.x + threadIdx.x;
    if (i < n) p[i] = 0;
}
__global__ void k_copy_int(const int* __restrict__ a, int* __restrict__ b, int n) {
    int i = blockIdx.x * blockDim.x + threadIdx.x;
    if (i < n) b[i] = a[i];
}
__global__ void k_hist(const int* __restrict__ dst, int* __restrict__ deg, int E) {
    int e = blockIdx.x * blockDim.x + threadIdx.x;
    if (e < E) atomicAdd(&deg[dst[e]], 1);
}
__global__ void k_exscan(const int* __restrict__ v, int* __restrict__ offs, int n) {
    __shared__ int wsum[32];
    __shared__ int carry;
    int t = threadIdx.x;
    if (t == 0) carry = 0;
    __syncthreads();
    for (int base = 0; base < n; base += 1024) {
        int i = base + t;
        int orig = (i < n) ? v[i] : 0;
        int x = orig;
        #pragma unroll
        for (int o = 1; o < 32; o <<= 1) {
            int y = __shfl_up_sync(0xffffffffu, x, o);
            if ((t & 31) >= o) x += y;
        }
        if ((t & 31) == 31) wsum[t >> 5] = x;
        __syncthreads();
        if (t < 32) {
            int w = wsum[t];
            #pragma unroll
            for (int o = 1; o < 32; o <<= 1) {
                int y = __shfl_up_sync(0xffffffffu, w, o);
                if (t >= o) w += y;
            }
            wsum[t] = w;
        }
        __syncthreads();
        int woff = (t >= 32) ? wsum[(t >> 5) - 1] : 0;
        int incl = x + woff + carry;
        if (i < n) offs[i] = incl - orig;
        __syncthreads();
        if (t == 1023) carry = incl;
        __syncthreads();
    }
    if (t == 0) offs[n] = carry;
}
__global__ void k_build(const int* __restrict__ dst, const int* __restrict__ src,
                        int* __restrict__ cursor, int* __restrict__ csr, int E) {
    int e = blockIdx.x * blockDim.x + threadIdx.x;
    if (e < E) {
        int p = atomicAdd(&cursor[dst[e]], 1);
        csr[p] = src[e];
    }
}
__global__ void k_init_test(const float* __restrict__ temb, float* __restrict__ h) {
    int i = blockIdx.x * blockDim.x + threadIdx.x;
    if (i < N_TEST * HD) h[i] = temb[i & 127];
}

// ---------------- encoder ----------------------------------------------------
__global__ void __launch_bounds__(256) k_encode(
    const int* __restrict__ label, const float* __restrict__ content,
    const float* __restrict__ emb, const float* __restrict__ Wc,
    const float* __restrict__ bc, float* __restrict__ h)
{
    extern __shared__ float sm[];
    float* Ws = sm;
    float* Cs = sm + 16384;
    int t = threadIdx.x;
    const float4* Wc4 = (const float4*)Wc;
    float4* Ws4 = (float4*)Ws;
    #pragma unroll
    for (int i = 0; i < 16; i++) Ws4[t + 256 * i] = Wc4[t + 256 * i];
    int n0 = blockIdx.x * 16;
    const float4* C4 = (const float4*)content + (size_t)n0 * 64;
    float4* Cs4 = (float4*)Cs;
    #pragma unroll
    for (int i = 0; i < 4; i++) Cs4[t + 256 * i] = C4[t + 256 * i];
    __syncthreads();
    int node = t >> 4, c = t & 15;
    const float* crow = &Cs[node * 256];
    float a0 = bc[c], a1 = bc[c + 16], a2 = bc[c + 32], a3 = bc[c + 48];
    #pragma unroll 4
    for (int k = 0; k < 256; k++) {
        float cv = crow[k];
        const float* wr = &Ws[k * 64];
        a0 += cv * wr[c];
        a1 += cv * wr[c + 16];
        a2 += cv * wr[c + 32];
        a3 += cv * wr[c + 48];
    }
    int gn = n0 + node;
    int lab = label[gn];
    float* hr = &h[(size_t)gn * HD];
    const float* er = &emb[(size_t)lab * 64];
    hr[c]      = er[c];
    hr[c + 16] = er[c + 16];
    hr[c + 32] = er[c + 32];
    hr[c + 48] = er[c + 48];
    hr[64 + c]      = a0;
    hr[64 + c + 16] = a1;
    hr[64 + c + 32] = a2;
    hr[64 + c + 48] = a3;
}

// ---------------- GEMM with fused epilogue ----------------------------------
// out[Mx128] = A[Mx128] @ W[128x128]  (+AddIn)(+bias)(relu)(+res)(save res)
__global__ void __launch_bounds__(256) k_gemm_ep(
    const float* __restrict__ A, const float* __restrict__ W,
    const float* __restrict__ AddIn, const float* __restrict__ bias,
    const float* __restrict__ res, float* __restrict__ out,
    float* __restrict__ res_out, int M, int flags)
{
    extern __shared__ float sm[];
    float* Ws = sm;            // 128*128
    float* As = sm + 16384;    // 64*132
    int t = threadIdx.x;
    const float4* W4 = (const float4*)W;
    float4* Ws4 = (float4*)Ws;
    #pragma unroll
    for (int i = 0; i < 16; i++) Ws4[t + 256 * i] = W4[t + 256 * i];
    int m0 = blockIdx.x * 64;
    #pragma unroll
    for (int i = 0; i < 8; i++) {
        int idx = t + 256 * i;
        int r = idx >> 5, cc = idx & 31;
        int gr = m0 + r;
        float4 v = (gr < M) ? ((const float4*)A)[(size_t)gr * 32 + cc]
                            : make_float4(0.f, 0.f, 0.f, 0.f);
        *(float4*)&As[r * 132 + cc * 4] = v;
    }
    __syncthreads();
    int c0 = (t & 31) * 4;
    int r0 = (t >> 5) * 8;
    float acc[8][4];
    #pragma unroll
    for (int i = 0; i < 8; i++) { acc[i][0] = acc[i][1] = acc[i][2] = acc[i][3] = 0.f; }
    #pragma unroll 2
    for (int k = 0; k < 128; k++) {
        float4 w = *(const float4*)&Ws[k * 128 + c0];
        #pragma unroll
        for (int i = 0; i < 8; i++) {
            float a = As[(r0 + i) * 132 + k];
            acc[i][0] += a * w.x;
            acc[i][1] += a * w.y;
            acc[i][2] += a * w.z;
            acc[i][3] += a * w.w;
        }
    }
    float4 bb = make_float4(0.f, 0.f, 0.f, 0.f);
    if (flags & F_BIAS) bb = *(const float4*)&bias[c0];
    #pragma unroll
    for (int i = 0; i < 8; i++) {
        int gr = m0 + r0 + i;
        if (gr < M) {
            size_t o = (size_t)gr * HD + c0;
            float4 v = make_float4(acc[i][0] + bb.x, acc[i][1] + bb.y,
                                   acc[i][2] + bb.z, acc[i][3] + bb.w);
            if (flags & F_ADDIN) {
                float4 d = *(const float4*)&AddIn[o];
                v.x += d.x; v.y += d.y; v.z += d.z; v.w += d.w;
            }
            if (flags & F_RELU) {
                v.x = fmaxf(v.x, 0.f); v.y = fmaxf(v.y, 0.f);
                v.z = fmaxf(v.z, 0.f); v.w = fmaxf(v.w, 0.f);
            }
            if (flags & F_ADDRES) {
                float4 rv = *(const float4*)&res[o];
                v.x += rv.x; v.y += rv.y; v.z += rv.z; v.w += rv.w;
            }
            *(float4*)&out[o] = v;
            if (flags & F_SAVE) *(float4*)&res_out[o] = v;
        }
    }
}

// ---------------- mean aggregation: out[node] = mean over csr of X rows -----
__global__ void k_agg(const float* __restrict__ X,
                      const int* __restrict__ offs, const int* __restrict__ csr,
                      float* __restrict__ out, int n)
{
    int node = (blockIdx.x * blockDim.x + threadIdx.x) >> 5;
    if (node >= n) return;
    int lane = threadIdx.x & 31;
    int s0 = offs[node], s1 = offs[node + 1];
    float4 a = make_float4(0.f, 0.f, 0.f, 0.f);
    for (int e0 = s0; e0 < s1; e0 += 32) {
        int idx = (e0 + lane < s1) ? csr[e0 + lane] : 0;
        int m = min(32, s1 - e0);
        for (int j = 0; j < m; j++) {
            int s = __shfl_sync(0xffffffffu, idx, j);
            float4 v = *(const float4*)&X[(size_t)s * HD + lane * 4];
            a.x += v.x; a.y += v.y; a.z += v.z; a.w += v.w;
        }
    }
    float inv = 1.f / (float)((s1 - s0) > 0 ? (s1 - s0) : 1);
    *(float4*)&out[(size_t)node * HD + lane * 4] =
        make_float4(a.x * inv, a.y * inv, a.z * inv, a.w * inv);
}

// ---------------- decoder ----------------------------------------------------
__global__ void k_decode(const float* __restrict__ h, const float* __restrict__ dW,
                         const float* __restrict__ db, float* __restrict__ logits,
                         float* __restrict__ pred, int write_pred)
{
    int node = (blockIdx.x * blockDim.x + threadIdx.x) >> 5;
    if (node >= N_AST) return;
    int lane = threadIdx.x & 31;
    float4 v = *(const float4*)&h[(size_t)node * HD + lane * 4];
    float l0 = 0.f, l1 = 0.f;
    const float* hv = &v.x;
    #pragma unroll
    for (int j = 0; j < 4; j++) {
        int k = lane * 4 + j;
        float2 w = *(const float2*)&dW[k * 2];
        l0 += hv[j] * w.x;
        l1 += hv[j] * w.y;
    }
    #pragma unroll
    for (int o = 16; o; o >>= 1) {
        l0 += __shfl_xor_sync(0xffffffffu, l0, o);
        l1 += __shfl_xor_sync(0xffffffffu, l1, o);
    }
    if (lane == 0) {
        l0 += db[0];
        l1 += db[1];
        logits[node * 2]     = l0;
        logits[node * 2 + 1] = l1;
        if (write_pred) {
            float m = fmaxf(l0, l1);
            float e0 = expf(l0 - m), e1 = expf(l1 - m);
            float s = e0 + e1;
            pred[node * 2]     = e0 / s;
            pred[node * 2 + 1] = e1 / s;
        }
    }
}

// ---------------- launch ----------------------------------------------------
extern "C" void kernel_launch(void* const* d_in, const int* in_sizes, int n_in,
                              void* d_out, int out_size)
{
    const int*   ast_label   = (const int*)d_in[0];
    const float* ast_content = (const float*)d_in[1];
    const int* src_aa = (const int*)d_in[2];
    const int* dst_aa = (const int*)d_in[3];
    const int* src_at = (const int*)d_in[4];
    const int* dst_at = (const int*)d_in[5];
    const int* src_ta = (const int*)d_in[6];
    const int* dst_ta = (const int*)d_in[7];
    int E_aa = in_sizes[2], E_at = in_sizes[4], E_ta = in_sizes[6];

    int p = 8;
    if (n_in > 8 && in_sizes[8] == 1) p = 9;
    const float* emb    = (const float*)d_in[p + 0];
    const float* Wc     = (const float*)d_in[p + 1];
    const float* bc     = (const float*)d_in[p + 2];
    const float* temb   = (const float*)d_in[p + 3];
    const float* W_aa   = (const float*)d_in[p + 4];
    const float* W_at   = (const float*)d_in[p + 5];
    const float* W_ta   = (const float*)d_in[p + 6];
    const float* b_ast  = (const float*)d_in[p + 7];
    const float* b_test = (const float*)d_in[p + 8];
    const float* dW     = (const float*)d_in[p + 9];
    const float* db     = (const float*)d_in[p + 10];

    float* F = nullptr;
    int*   I = nullptr;
    cudaGetSymbolAddress((void**)&F, g_f);
    cudaGetSymbolAddress((void**)&I, g_i);

    cudaFuncSetAttribute(k_gemm_ep, cudaFuncAttributeMaxDynamicSharedMemorySize, 99328);
    cudaFuncSetAttribute(k_encode,  cudaFuncAttributeMaxDynamicSharedMemorySize, 81920);

    float* hA  = F + F_HA;   float* hB  = F + F_HB;
    float* rA  = F + F_RA;   float* S   = F + F_S;
    float* Mta = F + F_MTA;
    float* hTA = F + F_HTA;  float* hTB = F + F_HTB;
    float* rT  = F + F_RT;   float* Xta = F + F_XTA;
    float* St  = F + F_ST;

    int* off_aa = I + I_OFF_AA; int* off_ta = I + I_OFF_TA; int* off_at = I + I_OFF_AT;
    int* cur_aa = I + I_CUR_AA; int* cur_ta = I + I_CUR_TA; int* cur_at = I + I_CUR_AT;
    int* csr_aa = I + I_CSR_AA; int* csr_ta = I + I_CSR_TA; int* csr_at = I + I_CSR_AT;

    // --- CSR build ---
    k_zero_int<<<div_up(N_AST, 256), 256>>>(cur_aa, N_AST);
    k_zero_int<<<div_up(N_AST, 256), 256>>>(cur_ta, N_AST);
    k_zero_int<<<div_up(N_TEST, 256), 256>>>(cur_at, N_TEST);
    k_hist<<<div_up(E_aa, 256), 256>>>(dst_aa, cur_aa, E_aa);
    k_hist<<<div_up(E_ta, 256), 256>>>(dst_ta, cur_ta, E_ta);
    k_hist<<<div_up(E_at, 256), 256>>>(dst_at, cur_at, E_at);
    k_exscan<<<1, 1024>>>(cur_aa, off_aa, N_AST);
    k_exscan<<<1, 1024>>>(cur_ta, off_ta, N_AST);
    k_exscan<<<1, 1024>>>(cur_at, off_at, N_TEST);
    k_copy_int<<<div_up(N_AST, 256), 256>>>(off_aa, cur_aa, N_AST);
    k_copy_int<<<div_up(N_AST, 256), 256>>>(off_ta, cur_ta, N_AST);
    k_copy_int<<<div_up(N_TEST, 256), 256>>>(off_at, cur_at, N_TEST);
    k_build<<<div_up(E_aa, 256), 256>>>(dst_aa, src_aa, cur_aa, csr_aa, E_aa);
    k_build<<<div_up(E_ta, 256), 256>>>(dst_ta, src_ta, cur_ta, csr_ta, E_ta);
    k_build<<<div_up(E_at, 256), 256>>>(dst_at, src_at, cur_at, csr_at, E_at);

    // --- encode ---
    k_encode<<<N_AST / 16, 256, 81920>>>(ast_label, ast_content, emb, Wc, bc, hA);
    k_init_test<<<div_up(N_TEST * HD, 256), 256>>>(temb, hTA);

    // --- 5 GCN layers (aggregate-first where it shrinks GEMM M) ---
    const float* ia = hA; const float* it = hTA;
    float* oa = hB; float* ot = hTB;
    for (int l = 0; l < NLAYERS; l++) {
        int add  = (l == 1 || l == 3) ? F_ADDRES : 0;
        int save = (l == 0 || l == 2) ? F_SAVE : 0;
        // S = mean_aa(h_ast); St = mean_at(h_ast)  (both read OLD h_ast)
        k_agg<<<div_up(N_AST * 32, 256), 256>>>(ia, off_aa, csr_aa, S, N_AST);
        k_agg<<<div_up(N_TEST * 32, 256), 256>>>(ia, off_at, csr_at, St, N_TEST);
        // Xta = h_test @ W_ta (plain); Mta = mean_ta(Xta)
        k_gemm_ep<<<div_up(N_TEST, 64), 256, 99328>>>(it, W_ta + (size_t)l * HD * HD,
            nullptr, nullptr, nullptr, Xta, nullptr, N_TEST, 0);
        k_agg<<<div_up(N_AST * 32, 256), 256>>>(Xta, off_ta, csr_ta, Mta, N_AST);
        // h_ast' = relu(S @ W_aa + Mta + b_ast) (+res)
        k_gemm_ep<<<div_up(N_AST, 64), 256, 99328>>>(S, W_aa + (size_t)l * HD * HD,
            Mta, b_ast + l * HD, rA, oa, rA, N_AST,
            F_ADDIN | F_BIAS | F_RELU | add | save);
        // h_test' = relu(St @ W_at + b_test) (+res)
        k_gemm_ep<<<div_up(N_TEST, 64), 256, 99328>>>(St, W_at + (size_t)l * HD * HD,
            nullptr, b_test + l * HD, rT, ot, rT, N_TEST,
            F_BIAS | F_RELU | add | save);
        const float* ta = ia; ia = oa; oa = (float*)ta;
        const float* tt = it; it = ot; ot = (float*)tt;
    }

    // --- decode ---
    float* logits = (float*)d_out;
    int write_pred = (out_size >= 4 * N_AST);
    float* pred = logits + 2 * N_AST;
    k_decode<<<div_up(N_AST * 32, 256), 256>>>(ia, dW, db, logits, pred, write_pred);
}